// round 6
// baseline (speedup 1.0000x reference)
#include <cuda_runtime.h>

// Problem dims
static constexpr int Bn = 32, Tn = 10, Dn = 10, Un = 50, Pn = 50, En = 256;
static constexpr int Rr = 64;    // padded row count (U and P padded to 64)
static constexpr int SA = 260;   // row stride (floats) for X/K/V/H tiles
static constexpr int SSs = 68;   // row stride for score tile (64 cols + pad)
static constexpr int SWs = 260;  // stride for staged weight tile [32 k][256 n]; 2 buffers fit V region

static constexpr int SMEM_FLOATS = 3 * Rr * SA + Rr * SSs;   // 49920 + 4352 = 54272
static constexpr int SMEM_BYTES  = SMEM_FLOATS * 4;          // 217088 B

// ---- packed f32x2 helpers (Blackwell FFMA2 — PTX-only path) ----
__device__ __forceinline__ unsigned long long pk2(float lo, float hi) {
    unsigned long long r;
    asm("mov.b64 %0, {%1, %2};" : "=l"(r) : "f"(lo), "f"(hi));
    return r;
}
__device__ __forceinline__ void fma2(unsigned long long &acc, unsigned long long a, unsigned long long b) {
    asm("fma.rn.f32x2 %0, %1, %2, %0;" : "+l"(acc) : "l"(a), "l"(b));
}
__device__ __forceinline__ float2 upk(unsigned long long v) {
    float lo, hi;
    asm("mov.b64 {%0, %1}, %2;" : "=f"(lo), "=f"(hi) : "l"(v));
    return make_float2(lo, hi);
}
__device__ __forceinline__ float wsum(float v) {
#pragma unroll
    for (int o = 16; o > 0; o >>= 1) v += __shfl_xor_sync(0xffffffffu, v, o);
    return v;
}
__device__ __forceinline__ float wmax(float v) {
#pragma unroll
    for (int o = 16; o > 0; o >>= 1) v = fmaxf(v, __shfl_xor_sync(0xffffffffu, v, o));
    return v;
}

// C[64][256] += A[64][256] * W^T, W global [256 n][256 k] row-major.
// W staged transposed ([k][n]) in 8 chunks of 32 k, double-buffered in sWb
// (2 x 32 x SWs floats). Thread tid stages W row n=tid (contiguous 128B LDG,
// lane-consecutive STS.32 -> conflict-free). One barrier per chunk; LDG of
// chunk c+1 issued before the barrier, STS after compute(c).
// Thread (tr = warp, tc = lane) owns rows tr*8..+7, cols tc*8..+7.
__device__ __forceinline__ void ffn_gemm(
    const float* __restrict__ Wg, const float* __restrict__ sA, float* __restrict__ sWb,
    unsigned long long acc[8][4], int tid, int tr, int tc)
{
    float4 wreg[8];
    const float* wrow = Wg + tid * En;
    // prologue: LDG chunk 0
#pragma unroll
    for (int i = 0; i < 8; ++i)
        wreg[i] = *reinterpret_cast<const float4*>(wrow + i * 4);
    __syncthreads();   // prior consumers of sWb region + producers of sA are done
    {
        float* dst0 = sWb + tid;
#pragma unroll
        for (int i = 0; i < 8; ++i) {
            float* dst = dst0 + (i * 4) * SWs;
            dst[0]       = wreg[i].x;
            dst[SWs]     = wreg[i].y;
            dst[2 * SWs] = wreg[i].z;
            dst[3 * SWs] = wreg[i].w;
        }
    }
    for (int c = 0; c < 8; ++c) {
        if (c < 7) {
#pragma unroll
            for (int i = 0; i < 8; ++i)
                wreg[i] = *reinterpret_cast<const float4*>(wrow + (c + 1) * 32 + i * 4);
        }
        __syncthreads();   // STS(c) visible; compute(c-1) finished on all warps
        const float* buf = sWb + (c & 1) * (32 * SWs);
        const float* sAr = sA + tr * 8 * SA + c * 32;
#pragma unroll 4
        for (int g = 0; g < 8; ++g) {           // 4 k-values per g
            float4 a4[8];
#pragma unroll
            for (int i = 0; i < 8; ++i)         // uniform (broadcast) float4 A loads
                a4[i] = *reinterpret_cast<const float4*>(sAr + i * SA + g * 4);
#pragma unroll
            for (int j = 0; j < 4; ++j) {
                const float* bp = buf + (g * 4 + j) * SWs + tc * 8;
                float4 b0 = *reinterpret_cast<const float4*>(bp);
                float4 b1 = *reinterpret_cast<const float4*>(bp + 4);
                unsigned long long w0 = pk2(b0.x, b0.y), w1 = pk2(b0.z, b0.w);
                unsigned long long w2 = pk2(b1.x, b1.y), w3 = pk2(b1.z, b1.w);
#pragma unroll
                for (int i = 0; i < 8; ++i) {
                    float a = (j == 0) ? a4[i].x : (j == 1) ? a4[i].y : (j == 2) ? a4[i].z : a4[i].w;
                    unsigned long long aa = pk2(a, a);
                    fma2(acc[i][0], aa, w0);
                    fma2(acc[i][1], aa, w1);
                    fma2(acc[i][2], aa, w2);
                    fma2(acc[i][3], aa, w3);
                }
            }
        }
        if (c < 7) {       // STS chunk c+1 into the buffer freed by compute(c-1)
            float* dst0 = sWb + ((c + 1) & 1) * (32 * SWs) + tid;
#pragma unroll
            for (int i = 0; i < 8; ++i) {
                float* dst = dst0 + (i * 4) * SWs;
                dst[0]       = wreg[i].x;
                dst[SWs]     = wreg[i].y;
                dst[2 * SWs] = wreg[i].z;
                dst[3 * SWs] = wreg[i].w;
            }
        }
    }
}

__global__ __launch_bounds__(256, 1)
void fusion_block_kernel(
    const float* __restrict__ Qg_, const float* __restrict__ Kg_,
    const float* __restrict__ Vg_, const float* __restrict__ Mg_,
    const float* __restrict__ W1, const float* __restrict__ b1,
    const float* __restrict__ W2, const float* __restrict__ b2,
    const float* __restrict__ ln1w, const float* __restrict__ ln1b,
    const float* __restrict__ ln2w, const float* __restrict__ ln2b,
    float* __restrict__ Out)
{
    extern __shared__ float sm[];
    float* sX = sm;                 // Q tile -> x (LN1 out) [64][SA]
    float* sK = sm + Rr * SA;       // K tile -> H (ffn hidden) [64][SA]
    float* sV = sm + 2 * Rr * SA;   // V tile -> W double buffer (2 x 32 x SWs)
    float* sS = sm + 3 * Rr * SA;   // scores [64][SSs]

    const int tid  = threadIdx.x;
    const int warp = tid >> 5;
    const int lane = tid & 31;

    const int bid = blockIdx.x;         // enumerates (b, t, d)
    const int bt  = bid / Dn;           // b*T + t
    const int d   = bid - bt * Dn;
    const int b   = bt / Tn;
    const int bd  = b * Dn + d;

    const float* Qg = Qg_ + (size_t)bt  * (Un * En);
    const float* Kg = Kg_ + (size_t)bd  * (Pn * En);
    const float* Vg = Vg_ + (size_t)bd  * (Pn * En);
    const float* Mg = Mg_ + (size_t)bid * (Un * Pn);
    float*       Og = Out + (size_t)bid * (Un * En);

    // ---- Load Q/K/V tiles (rows >= 50 zero-padded) ----
    for (int f = tid; f < Rr * (En / 4); f += 256) {
        int row = f >> 6;
        int c4  = (f & 63) << 2;
        float4 z = make_float4(0.f, 0.f, 0.f, 0.f);
        float4 q = z, k = z, v = z;
        if (row < Un) {
            q = *reinterpret_cast<const float4*>(Qg + row * En + c4);
            k = *reinterpret_cast<const float4*>(Kg + row * En + c4);
            v = *reinterpret_cast<const float4*>(Vg + row * En + c4);
        }
        *reinterpret_cast<float4*>(&sX[row * SA + c4]) = q;
        *reinterpret_cast<float4*>(&sK[row * SA + c4]) = k;
        *reinterpret_cast<float4*>(&sV[row * SA + c4]) = v;
    }
    __syncthreads();

    // ---- S = Q K^T / scale + mask ----
    // Lanes own u-rows {lane, lane+32} (stride SA -> conflict-free float4 LDS);
    // warps own 8 p-cols (K rows are warp-uniform broadcasts).
    {
        unsigned long long acc[2][8] = {};
        const float* q0p = sX + lane * SA;
        const float* q1p = sX + (lane + 32) * SA;
        const float* kp  = sK + warp * 8 * SA;
#pragma unroll 8
        for (int e4 = 0; e4 < En / 4; ++e4) {
            float4 q0 = *reinterpret_cast<const float4*>(q0p + e4 * 4);
            float4 q1 = *reinterpret_cast<const float4*>(q1p + e4 * 4);
            unsigned long long q0a = pk2(q0.x, q0.y), q0b = pk2(q0.z, q0.w);
            unsigned long long q1a = pk2(q1.x, q1.y), q1b = pk2(q1.z, q1.w);
#pragma unroll
            for (int j = 0; j < 8; ++j) {
                float4 kv = *reinterpret_cast<const float4*>(kp + j * SA + e4 * 4);
                unsigned long long ka = pk2(kv.x, kv.y), kb = pk2(kv.z, kv.w);
                fma2(acc[0][j], q0a, ka); fma2(acc[0][j], q0b, kb);
                fma2(acc[1][j], q1a, ka); fma2(acc[1][j], q1b, kb);
            }
        }
        // sqrt(256) + 1e-8 rounds to exactly 16.0f in fp32
        const float inv_scale = 1.0f / 16.0f;
#pragma unroll
        for (int i = 0; i < 2; ++i) {
            int u = lane + i * 32;
#pragma unroll
            for (int j = 0; j < 8; ++j) {
                float2 pv = upk(acc[i][j]);
                float s = (pv.x + pv.y) * inv_scale;
                int p = warp * 8 + j;
                if (u < Un && p < Pn) s += Mg[u * Pn + p];
                sS[u * SSs + p] = s;
            }
        }
    }
    __syncthreads();

    // ---- softmax over p (valid p < 50), zeros in pad cols ----
    {
#pragma unroll
        for (int r = 0; r < 8; ++r) {
            int row = warp * 8 + r;
            float v0 = sS[row * SSs + lane];                                   // p = lane < 50 always
            float v1 = (lane + 32 < Pn) ? sS[row * SSs + lane + 32] : -1e30f;  // p = lane+32
            float m  = wmax(fmaxf(v0, v1));
            float e0 = __expf(v0 - m);
            float e1 = (lane + 32 < Pn) ? __expf(v1 - m) : 0.f;
            float inv = 1.f / wsum(e0 + e1);
            sS[row * SSs + lane]      = e0 * inv;
            sS[row * SSs + lane + 32] = e1 * inv;   // 0 for p >= 50
        }
    }
    __syncthreads();

    const int tr = warp;   // row group (8 rows)
    const int tc = lane;   // col group (8 cols)

    // ---- v_att = S @ V ;  x = Q + v_att (in place in sX) ----
    {
        unsigned long long acc[8][4] = {};
        const float* sSr = sS + tr * 8 * SSs;
#pragma unroll 4
        for (int g = 0; g < 16; ++g) {          // 4 k-values per g
            float4 a4[8];
#pragma unroll
            for (int i = 0; i < 8; ++i)         // uniform float4 score loads
                a4[i] = *reinterpret_cast<const float4*>(sSr + i * SSs + g * 4);
#pragma unroll
            for (int j = 0; j < 4; ++j) {
                const float* bp = sV + (g * 4 + j) * SA + tc * 8;
                float4 b0 = *reinterpret_cast<const float4*>(bp);
                float4 b1 = *reinterpret_cast<const float4*>(bp + 4);
                unsigned long long w0 = pk2(b0.x, b0.y), w1 = pk2(b0.z, b0.w);
                unsigned long long w2 = pk2(b1.x, b1.y), w3 = pk2(b1.z, b1.w);
#pragma unroll
                for (int i = 0; i < 8; ++i) {
                    float a = (j == 0) ? a4[i].x : (j == 1) ? a4[i].y : (j == 2) ? a4[i].z : a4[i].w;
                    unsigned long long aa = pk2(a, a);
                    fma2(acc[i][0], aa, w0); fma2(acc[i][1], aa, w1);
                    fma2(acc[i][2], aa, w2); fma2(acc[i][3], aa, w3);
                }
            }
        }
#pragma unroll
        for (int i = 0; i < 8; ++i) {
            float* xp = &sX[(tr * 8 + i) * SA + tc * 8];
#pragma unroll
            for (int j2 = 0; j2 < 4; ++j2) {
                float2 v = upk(acc[i][j2]);
                xp[j2 * 2]     += v.x;
                xp[j2 * 2 + 1] += v.y;
            }
        }
    }
    __syncthreads();

    // ---- LN1 (one warp per row, 8 rows per warp) ----
    {
#pragma unroll
        for (int r = 0; r < 8; ++r) {
            int row = warp * 8 + r;
            float xv[8];
            float s = 0.f;
#pragma unroll
            for (int kk = 0; kk < 8; ++kk) { xv[kk] = sX[row * SA + lane + kk * 32]; s += xv[kk]; }
            float mu = wsum(s) * (1.f / En);
            float vs = 0.f;
#pragma unroll
            for (int kk = 0; kk < 8; ++kk) { float t = xv[kk] - mu; vs += t * t; }
            float rstd = rsqrtf(wsum(vs) * (1.f / En) + 1e-5f);
#pragma unroll
            for (int kk = 0; kk < 8; ++kk) {
                int col = lane + kk * 32;
                sX[row * SA + col] = (xv[kk] - mu) * rstd * ln1w[col] + ln1b[col];
            }
        }
    }
    // (first barrier inside ffn_gemm orders LN1 writes before FFN1 compute)

    // ---- FFN layer 1: H = relu(x @ W1^T + b1) -> sK ----
    {
        unsigned long long acc[8][4] = {};
        ffn_gemm(W1, sX, sV, acc, tid, tr, tc);
#pragma unroll
        for (int i = 0; i < 8; ++i) {
            int row = tr * 8 + i;
#pragma unroll
            for (int j2 = 0; j2 < 4; ++j2) {
                float2 v = upk(acc[i][j2]);
                int col = tc * 8 + j2 * 2;
                sK[row * SA + col]     = fmaxf(v.x + b1[col], 0.f);
                sK[row * SA + col + 1] = fmaxf(v.y + b1[col + 1], 0.f);
            }
        }
    }
    // (first barrier inside next ffn_gemm separates H writes from FFN2 compute)

    // ---- FFN layer 2: y = H @ W2^T + b2 + x (in place into sX) ----
    {
        unsigned long long acc[8][4] = {};
        ffn_gemm(W2, sK, sV, acc, tid, tr, tc);
#pragma unroll
        for (int i = 0; i < 8; ++i) {
            int row = tr * 8 + i;
#pragma unroll
            for (int j2 = 0; j2 < 4; ++j2) {
                float2 v = upk(acc[i][j2]);
                int col = tc * 8 + j2 * 2;
                sX[row * SA + col]     += v.x + b2[col];
                sX[row * SA + col + 1] += v.y + b2[col + 1];
            }
        }
    }
    __syncthreads();

    // ---- LN2 + store (valid rows only) ----
    {
#pragma unroll
        for (int r = 0; r < 8; ++r) {
            int row = warp * 8 + r;
            if (row >= Un) break;    // uniform per warp
            float xv[8];
            float s = 0.f;
#pragma unroll
            for (int kk = 0; kk < 8; ++kk) { xv[kk] = sX[row * SA + lane + kk * 32]; s += xv[kk]; }
            float mu = wsum(s) * (1.f / En);
            float vs = 0.f;
#pragma unroll
            for (int kk = 0; kk < 8; ++kk) { float t = xv[kk] - mu; vs += t * t; }
            float rstd = rsqrtf(wsum(vs) * (1.f / En) + 1e-5f);
#pragma unroll
            for (int kk = 0; kk < 8; ++kk) {
                int col = lane + kk * 32;
                Og[row * En + col] = (xv[kk] - mu) * rstd * ln2w[col] + ln2b[col];
            }
        }
    }
}

extern "C" void kernel_launch(void* const* d_in, const int* in_sizes, int n_in,
                              void* d_out, int out_size) {
    (void)in_sizes; (void)n_in; (void)out_size;
    cudaFuncSetAttribute(fusion_block_kernel,
                         cudaFuncAttributeMaxDynamicSharedMemorySize, SMEM_BYTES);
    fusion_block_kernel<<<Bn * Tn * Dn, 256, SMEM_BYTES>>>(
        (const float*)d_in[0],  // Q
        (const float*)d_in[1],  // K
        (const float*)d_in[2],  // V
        (const float*)d_in[3],  // attention_mask
        (const float*)d_in[4],  // W1
        (const float*)d_in[5],  // b1
        (const float*)d_in[6],  // W2
        (const float*)d_in[7],  // b2
        (const float*)d_in[8],  // ln1_w
        (const float*)d_in[9],  // ln1_b
        (const float*)d_in[10], // ln2_w
        (const float*)d_in[11], // ln2_b
        (float*)d_out);
}

// round 7
// speedup vs baseline: 1.4476x; 1.4476x over previous
#include <cuda_runtime.h>
#include <cstdint>

// Problem dims
static constexpr int Bn = 32, Tn = 10, Dn = 10, Un = 50, Pn = 50, En = 256;
static constexpr int Rr = 64;    // padded row count (U and P padded to 64)
static constexpr int SA = 260;   // row stride (floats) for X/K/V/H tiles (260 % 32 == 4)
static constexpr int SSs = 68;   // row stride for score tile
static constexpr int SWs = 264;  // stride for staged W tile [16 k][256 n] (264 % 32 == 8)

static constexpr int SMEM_FLOATS = 3 * Rr * SA + Rr * SSs;   // 54272
static constexpr int SMEM_BYTES  = SMEM_FLOATS * 4;          // 217088 B

// ---- packed f32x2 helpers (fp32 attention path) ----
__device__ __forceinline__ unsigned long long pk2(float lo, float hi) {
    unsigned long long r;
    asm("mov.b64 %0, {%1, %2};" : "=l"(r) : "f"(lo), "f"(hi));
    return r;
}
__device__ __forceinline__ void fma2(unsigned long long &acc, unsigned long long a, unsigned long long b) {
    asm("fma.rn.f32x2 %0, %1, %2, %0;" : "+l"(acc) : "l"(a), "l"(b));
}
__device__ __forceinline__ float2 upk(unsigned long long v) {
    float lo, hi;
    asm("mov.b64 {%0, %1}, %2;" : "=f"(lo), "=f"(hi) : "l"(v));
    return make_float2(lo, hi);
}
__device__ __forceinline__ float wsum(float v) {
#pragma unroll
    for (int o = 16; o > 0; o >>= 1) v += __shfl_xor_sync(0xffffffffu, v, o);
    return v;
}
__device__ __forceinline__ float wmax(float v) {
#pragma unroll
    for (int o = 16; o > 0; o >>= 1) v = fmaxf(v, __shfl_xor_sync(0xffffffffu, v, o));
    return v;
}

// ---- tf32 MMA helpers ----
__device__ __forceinline__ uint32_t f2tf(float f) {
    uint32_t r;
    asm("cvt.rna.tf32.f32 %0, %1;" : "=r"(r) : "f"(f));
    return r;
}
__device__ __forceinline__ void mma_tf32(float c[4],
                                         uint32_t a0, uint32_t a1, uint32_t a2, uint32_t a3,
                                         uint32_t b0, uint32_t b1) {
    asm("mma.sync.aligned.m16n8k8.row.col.f32.tf32.tf32.f32 "
        "{%0,%1,%2,%3}, {%4,%5,%6,%7}, {%8,%9}, {%0,%1,%2,%3};"
        : "+f"(c[0]), "+f"(c[1]), "+f"(c[2]), "+f"(c[3])
        : "r"(a0), "r"(a1), "r"(a2), "r"(a3), "r"(b0), "r"(b1));
}

// FFN GEMM via tf32 mma: C[64][256] = A[64][256] * W^T.
// W global [256 n][256 k] row-major; staged k-major (tf32 bits) into sWb,
// double-buffered 16-k chunks (2 x 16 x SWs floats), thread tid stages row
// n = tid (contiguous 64B LDG, lane-consecutive STS -> conflict-free).
// Warp tile: rows (warp&3)*16..+15, cols (warp>>2)*128..+127 (16 n8-tiles).
// Lane: g = lane>>2, t = lane&3 (PTX m16n8k8 fragment mapping).
// acc[nt][0..3]: C[g][2t], C[g][2t+1], C[g+8][2t], C[g+8][2t+1] of tile nt.
__device__ __forceinline__ void ffn_mma(
    const float* __restrict__ Wg, const float* __restrict__ sA, float* __restrict__ sWb,
    float acc[16][4], int tid, int g, int t, int mb, int nh)
{
    float4 wreg[4];
    const float* wrow = Wg + tid * En;
#pragma unroll
    for (int i = 0; i < 4; ++i)
        wreg[i] = *reinterpret_cast<const float4*>(wrow + i * 4);
    __syncthreads();   // prior phase done: sA final, sWb region free
    {
        uint32_t* dst = reinterpret_cast<uint32_t*>(sWb) + tid;
#pragma unroll
        for (int i = 0; i < 4; ++i) {
            dst[(i * 4 + 0) * SWs] = f2tf(wreg[i].x);
            dst[(i * 4 + 1) * SWs] = f2tf(wreg[i].y);
            dst[(i * 4 + 2) * SWs] = f2tf(wreg[i].z);
            dst[(i * 4 + 3) * SWs] = f2tf(wreg[i].w);
        }
    }
    for (int c = 0; c < 16; ++c) {
        if (c < 15) {
#pragma unroll
            for (int i = 0; i < 4; ++i)
                wreg[i] = *reinterpret_cast<const float4*>(wrow + (c + 1) * 16 + i * 4);
        }
        __syncthreads();   // STS(c) visible on all warps; compute(c-1) finished
        const uint32_t* buf = reinterpret_cast<const uint32_t*>(sWb) + (c & 1) * (16 * SWs);
        const float* sA0 = sA + (mb + g) * SA + c * 16;
        const float* sA1 = sA + (mb + g + 8) * SA + c * 16;
#pragma unroll
        for (int h = 0; h < 2; ++h) {           // two k8 groups per 16-k chunk
            uint32_t a0 = f2tf(sA0[h * 8 + t]);
            uint32_t a1 = f2tf(sA1[h * 8 + t]);
            uint32_t a2 = f2tf(sA0[h * 8 + t + 4]);
            uint32_t a3 = f2tf(sA1[h * 8 + t + 4]);
            const uint32_t* b0p = buf + (h * 8 + t) * SWs + nh * 128 + g;
            const uint32_t* b1p = b0p + 4 * SWs;
#pragma unroll
            for (int nt = 0; nt < 16; ++nt)
                mma_tf32(acc[nt], a0, a1, a2, a3, b0p[nt * 8], b1p[nt * 8]);
        }
        if (c < 15) {      // stage chunk c+1 into buffer freed by compute(c-1)
            uint32_t* dst = reinterpret_cast<uint32_t*>(sWb) + ((c + 1) & 1) * (16 * SWs) + tid;
#pragma unroll
            for (int i = 0; i < 4; ++i) {
                dst[(i * 4 + 0) * SWs] = f2tf(wreg[i].x);
                dst[(i * 4 + 1) * SWs] = f2tf(wreg[i].y);
                dst[(i * 4 + 2) * SWs] = f2tf(wreg[i].z);
                dst[(i * 4 + 3) * SWs] = f2tf(wreg[i].w);
            }
        }
    }
}

__global__ __launch_bounds__(256, 1)
void fusion_block_kernel(
    const float* __restrict__ Qg_, const float* __restrict__ Kg_,
    const float* __restrict__ Vg_, const float* __restrict__ Mg_,
    const float* __restrict__ W1, const float* __restrict__ b1,
    const float* __restrict__ W2, const float* __restrict__ b2,
    const float* __restrict__ ln1w, const float* __restrict__ ln1b,
    const float* __restrict__ ln2w, const float* __restrict__ ln2b,
    float* __restrict__ Out)
{
    extern __shared__ float sm[];
    float* sX = sm;                 // Q tile -> x (LN1 out, fp32 residual) [64][SA]
    float* sK = sm + Rr * SA;       // K tile -> H (ffn hidden, fp32) [64][SA]
    float* sV = sm + 2 * Rr * SA;   // V tile -> W double buffer (2 x 16 x SWs)
    float* sS = sm + 3 * Rr * SA;   // scores [64][SSs]

    const int tid  = threadIdx.x;
    const int warp = tid >> 5;
    const int lane = tid & 31;

    const int bid = blockIdx.x;         // enumerates (b, t, d)
    const int bt  = bid / Dn;           // b*T + t
    const int d   = bid - bt * Dn;
    const int b   = bt / Tn;
    const int bd  = b * Dn + d;

    const float* Qg = Qg_ + (size_t)bt  * (Un * En);
    const float* Kg = Kg_ + (size_t)bd  * (Pn * En);
    const float* Vg = Vg_ + (size_t)bd  * (Pn * En);
    const float* Mg = Mg_ + (size_t)bid * (Un * Pn);
    float*       Og = Out + (size_t)bid * (Un * En);

    // ---- Load Q/K/V tiles (rows >= 50 zero-padded) ----
    for (int f = tid; f < Rr * (En / 4); f += 256) {
        int row = f >> 6;
        int c4  = (f & 63) << 2;
        float4 z = make_float4(0.f, 0.f, 0.f, 0.f);
        float4 q = z, k = z, v = z;
        if (row < Un) {
            q = *reinterpret_cast<const float4*>(Qg + row * En + c4);
            k = *reinterpret_cast<const float4*>(Kg + row * En + c4);
            v = *reinterpret_cast<const float4*>(Vg + row * En + c4);
        }
        *reinterpret_cast<float4*>(&sX[row * SA + c4]) = q;
        *reinterpret_cast<float4*>(&sK[row * SA + c4]) = k;
        *reinterpret_cast<float4*>(&sV[row * SA + c4]) = v;
    }
    __syncthreads();

    // ---- S = Q K^T / scale + mask (fp32 FFMA2) ----
    {
        unsigned long long acc[2][8] = {};
        const float* q0p = sX + lane * SA;
        const float* q1p = sX + (lane + 32) * SA;
        const float* kp  = sK + warp * 8 * SA;
#pragma unroll 8
        for (int e4 = 0; e4 < En / 4; ++e4) {
            float4 q0 = *reinterpret_cast<const float4*>(q0p + e4 * 4);
            float4 q1 = *reinterpret_cast<const float4*>(q1p + e4 * 4);
            unsigned long long q0a = pk2(q0.x, q0.y), q0b = pk2(q0.z, q0.w);
            unsigned long long q1a = pk2(q1.x, q1.y), q1b = pk2(q1.z, q1.w);
#pragma unroll
            for (int j = 0; j < 8; ++j) {
                float4 kv = *reinterpret_cast<const float4*>(kp + j * SA + e4 * 4);
                unsigned long long ka = pk2(kv.x, kv.y), kb = pk2(kv.z, kv.w);
                fma2(acc[0][j], q0a, ka); fma2(acc[0][j], q0b, kb);
                fma2(acc[1][j], q1a, ka); fma2(acc[1][j], q1b, kb);
            }
        }
        const float inv_scale = 1.0f / 16.0f;  // sqrt(256)+1e-8 == 16.0f in fp32
#pragma unroll
        for (int i = 0; i < 2; ++i) {
            int u = lane + i * 32;
#pragma unroll
            for (int j = 0; j < 8; ++j) {
                float2 pv = upk(acc[i][j]);
                float s = (pv.x + pv.y) * inv_scale;
                int p = warp * 8 + j;
                if (u < Un && p < Pn) s += Mg[u * Pn + p];
                sS[u * SSs + p] = s;
            }
        }
    }
    __syncthreads();

    // ---- softmax over p (valid p < 50), zeros in pad cols ----
    {
#pragma unroll
        for (int r = 0; r < 8; ++r) {
            int row = warp * 8 + r;
            float v0 = sS[row * SSs + lane];
            float v1 = (lane + 32 < Pn) ? sS[row * SSs + lane + 32] : -1e30f;
            float m  = wmax(fmaxf(v0, v1));
            float e0 = __expf(v0 - m);
            float e1 = (lane + 32 < Pn) ? __expf(v1 - m) : 0.f;
            float inv = 1.f / wsum(e0 + e1);
            sS[row * SSs + lane]      = e0 * inv;
            sS[row * SSs + lane + 32] = e1 * inv;
        }
    }
    __syncthreads();

    // ---- v_att = S @ V ;  x = Q + v_att (fp32 FFMA2, in place in sX) ----
    {
        const int tr = warp, tc = lane;
        unsigned long long acc[8][4] = {};
        const float* sSr = sS + tr * 8 * SSs;
#pragma unroll 4
        for (int g2 = 0; g2 < 16; ++g2) {
            float4 a4[8];
#pragma unroll
            for (int i = 0; i < 8; ++i)
                a4[i] = *reinterpret_cast<const float4*>(sSr + i * SSs + g2 * 4);
#pragma unroll
            for (int j = 0; j < 4; ++j) {
                const float* bp = sV + (g2 * 4 + j) * SA + tc * 8;
                float4 b0 = *reinterpret_cast<const float4*>(bp);
                float4 b1 = *reinterpret_cast<const float4*>(bp + 4);
                unsigned long long w0 = pk2(b0.x, b0.y), w1 = pk2(b0.z, b0.w);
                unsigned long long w2 = pk2(b1.x, b1.y), w3 = pk2(b1.z, b1.w);
#pragma unroll
                for (int i = 0; i < 8; ++i) {
                    float a = (j == 0) ? a4[i].x : (j == 1) ? a4[i].y : (j == 2) ? a4[i].z : a4[i].w;
                    unsigned long long aa = pk2(a, a);
                    fma2(acc[i][0], aa, w0); fma2(acc[i][1], aa, w1);
                    fma2(acc[i][2], aa, w2); fma2(acc[i][3], aa, w3);
                }
            }
        }
#pragma unroll
        for (int i = 0; i < 8; ++i) {
            float* xp = &sX[(tr * 8 + i) * SA + tc * 8];
#pragma unroll
            for (int j2 = 0; j2 < 4; ++j2) {
                float2 v = upk(acc[i][j2]);
                xp[j2 * 2]     += v.x;
                xp[j2 * 2 + 1] += v.y;
            }
        }
    }
    __syncthreads();

    // ---- LN1 (one warp per row, 8 rows per warp) ----
    {
#pragma unroll
        for (int r = 0; r < 8; ++r) {
            int row = warp * 8 + r;
            float xv[8];
            float s = 0.f;
#pragma unroll
            for (int kk = 0; kk < 8; ++kk) { xv[kk] = sX[row * SA + lane + kk * 32]; s += xv[kk]; }
            float mu = wsum(s) * (1.f / En);
            float vs = 0.f;
#pragma unroll
            for (int kk = 0; kk < 8; ++kk) { float t2 = xv[kk] - mu; vs += t2 * t2; }
            float rstd = rsqrtf(wsum(vs) * (1.f / En) + 1e-5f);
#pragma unroll
            for (int kk = 0; kk < 8; ++kk) {
                int col = lane + kk * 32;
                sX[row * SA + col] = (xv[kk] - mu) * rstd * ln1w[col] + ln1b[col];
            }
        }
    }
    // (first barrier inside ffn_mma orders LN1 writes before FFN1 compute)

    const int g  = lane >> 2;     // fragment group row 0..7
    const int t  = lane & 3;      // thread-in-group 0..3
    const int mb = (warp & 3) * 16;   // warp's m base row
    const int nh = warp >> 1 >> 1;    // warp's n half (0 or 1)

    // ---- FFN layer 1: H = relu(x @ W1^T + b1) -> sK (fp32) ----
    {
        float acc[16][4];
#pragma unroll
        for (int nt = 0; nt < 16; ++nt)
            acc[nt][0] = acc[nt][1] = acc[nt][2] = acc[nt][3] = 0.f;
        ffn_mma(W1, sX, sV, acc, tid, g, t, mb, nh);
#pragma unroll
        for (int nt = 0; nt < 16; ++nt) {
            int col = nh * 128 + nt * 8 + 2 * t;
            float bb0 = __ldg(b1 + col), bb1 = __ldg(b1 + col + 1);
            sK[(mb + g) * SA + col]         = fmaxf(acc[nt][0] + bb0, 0.f);
            sK[(mb + g) * SA + col + 1]     = fmaxf(acc[nt][1] + bb1, 0.f);
            sK[(mb + g + 8) * SA + col]     = fmaxf(acc[nt][2] + bb0, 0.f);
            sK[(mb + g + 8) * SA + col + 1] = fmaxf(acc[nt][3] + bb1, 0.f);
        }
    }
    // (first barrier inside next ffn_mma separates H writes from FFN2 compute)

    // ---- FFN layer 2: y = H @ W2^T + b2 + x (in place into sX) ----
    {
        float acc[16][4];
#pragma unroll
        for (int nt = 0; nt < 16; ++nt)
            acc[nt][0] = acc[nt][1] = acc[nt][2] = acc[nt][3] = 0.f;
        ffn_mma(W2, sK, sV, acc, tid, g, t, mb, nh);
#pragma unroll
        for (int nt = 0; nt < 16; ++nt) {
            int col = nh * 128 + nt * 8 + 2 * t;
            float bb0 = __ldg(b2 + col), bb1 = __ldg(b2 + col + 1);
            sX[(mb + g) * SA + col]         += acc[nt][0] + bb0;
            sX[(mb + g) * SA + col + 1]     += acc[nt][1] + bb1;
            sX[(mb + g + 8) * SA + col]     += acc[nt][2] + bb0;
            sX[(mb + g + 8) * SA + col + 1] += acc[nt][3] + bb1;
        }
    }
    __syncthreads();

    // ---- LN2 + store (valid rows only) ----
    {
#pragma unroll
        for (int r = 0; r < 8; ++r) {
            int row = warp * 8 + r;
            if (row >= Un) break;    // uniform per warp
            float xv[8];
            float s = 0.f;
#pragma unroll
            for (int kk = 0; kk < 8; ++kk) { xv[kk] = sX[row * SA + lane + kk * 32]; s += xv[kk]; }
            float mu = wsum(s) * (1.f / En);
            float vs = 0.f;
#pragma unroll
            for (int kk = 0; kk < 8; ++kk) { float t2 = xv[kk] - mu; vs += t2 * t2; }
            float rstd = rsqrtf(wsum(vs) * (1.f / En) + 1e-5f);
#pragma unroll
            for (int kk = 0; kk < 8; ++kk) {
                int col = lane + kk * 32;
                Og[row * En + col] = (xv[kk] - mu) * rstd * ln2w[col] + ln2b[col];
            }
        }
    }
}

extern "C" void kernel_launch(void* const* d_in, const int* in_sizes, int n_in,
                              void* d_out, int out_size) {
    (void)in_sizes; (void)n_in; (void)out_size;
    cudaFuncSetAttribute(fusion_block_kernel,
                         cudaFuncAttributeMaxDynamicSharedMemorySize, SMEM_BYTES);
    fusion_block_kernel<<<Bn * Tn * Dn, 256, SMEM_BYTES>>>(
        (const float*)d_in[0],  // Q
        (const float*)d_in[1],  // K
        (const float*)d_in[2],  // V
        (const float*)d_in[3],  // attention_mask
        (const float*)d_in[4],  // W1
        (const float*)d_in[5],  // b1
        (const float*)d_in[6],  // W2
        (const float*)d_in[7],  // b2
        (const float*)d_in[8],  // ln1_w
        (const float*)d_in[9],  // ln1_b
        (const float*)d_in[10], // ln2_w
        (const float*)d_in[11], // ln2_b
        (float*)d_out);
}

// round 8
// speedup vs baseline: 1.7477x; 1.2073x over previous
#include <cuda_runtime.h>
#include <cstdint>

// Problem dims
static constexpr int Bn = 32, Tn = 10, Dn = 10, Un = 50, Pn = 50, En = 256;
static constexpr int Rr = 64;    // padded rows (U and P padded to 64)
static constexpr int SA = 260;   // sX/sK stride (260 % 32 == 4 -> col-major-B & A frags conflict-free)
static constexpr int SV = 264;   // sV stride  (264 % 32 == 8 -> k-major-B frags conflict-free)
static constexpr int SSs = 68;   // score stride (68 % 32 == 4)
static constexpr int SWs = 264;  // staged-W stride (8 mod 32)

// sX[64][SA] + sK[64][SA] + sV region (max(64*SV, 2*32*SWs) = 16896) + sS[64][SSs]
static constexpr int SMEM_FLOATS = 2 * Rr * SA + Rr * SV + Rr * SSs;  // 54528
static constexpr int SMEM_BYTES  = SMEM_FLOATS * 4;                   // 218112

__device__ __forceinline__ float wsum(float v) {
#pragma unroll
    for (int o = 16; o > 0; o >>= 1) v += __shfl_xor_sync(0xffffffffu, v, o);
    return v;
}
__device__ __forceinline__ float wmax(float v) {
#pragma unroll
    for (int o = 16; o > 0; o >>= 1) v = fmaxf(v, __shfl_xor_sync(0xffffffffu, v, o));
    return v;
}

// ---- tf32 MMA helpers ----
__device__ __forceinline__ uint32_t f2tf(float f) {
    uint32_t r;
    asm("cvt.rna.tf32.f32 %0, %1;" : "=r"(r) : "f"(f));
    return r;
}
__device__ __forceinline__ float tfr(float f) {          // round-to-tf32, keep as float bits
    return __uint_as_float(f2tf(f));
}
__device__ __forceinline__ void mma_tf32(float c[4],
                                         uint32_t a0, uint32_t a1, uint32_t a2, uint32_t a3,
                                         uint32_t b0, uint32_t b1) {
    asm("mma.sync.aligned.m16n8k8.row.col.f32.tf32.tf32.f32 "
        "{%0,%1,%2,%3}, {%4,%5,%6,%7}, {%8,%9}, {%0,%1,%2,%3};"
        : "+f"(c[0]), "+f"(c[1]), "+f"(c[2]), "+f"(c[3])
        : "r"(a0), "r"(a1), "r"(a2), "r"(a3), "r"(b0), "r"(b1));
}

// FFN GEMM: C[64][256] = A[64][256] * W^T (W global [256n][256k] row-major).
// W staged as tf32 bits, k-major [32k][256n], double-buffered (2 x 32 x SWs = sV region),
// thread tid stages row n=tid (128B LDG, lane-consecutive STS). 8 chunks, 1 barrier each.
// Warp tile m32 x n64: mb=(warp&1)*32, nbase=(warp>>1)*64. Frag map (validated R7):
// g=lane>>2, t=lane&3; A: a0(g,t) a1(g+8,t) a2(g,t+4) a3(g+8,t+4); B: b0(t,g) b1(t+4,g);
// C: c0(g,2t) c1(g,2t+1) c2(g+8,2t) c3(g+8,2t+1).
template<bool CVT_A>
__device__ __forceinline__ void ffn_mma(
    const float* __restrict__ Wg, const float* __restrict__ sA, float* __restrict__ sWb,
    float acc[2][8][4], int tid, int g, int t, int mb, int nbase)
{
    float4 wreg[8];
    const float* wrow = Wg + tid * En;
#pragma unroll
    for (int i = 0; i < 8; ++i)
        wreg[i] = *reinterpret_cast<const float4*>(wrow + i * 4);
    __syncthreads();   // prior phase done: sA final, sWb (V) region free
    uint32_t* base = reinterpret_cast<uint32_t*>(sWb);
    {
        uint32_t* dst = base + tid;
#pragma unroll
        for (int i = 0; i < 8; ++i) {
            dst[(i * 4 + 0) * SWs] = f2tf(wreg[i].x);
            dst[(i * 4 + 1) * SWs] = f2tf(wreg[i].y);
            dst[(i * 4 + 2) * SWs] = f2tf(wreg[i].z);
            dst[(i * 4 + 3) * SWs] = f2tf(wreg[i].w);
        }
    }
    for (int c = 0; c < 8; ++c) {
        if (c < 7) {
#pragma unroll
            for (int i = 0; i < 8; ++i)
                wreg[i] = *reinterpret_cast<const float4*>(wrow + (c + 1) * 32 + i * 4);
        }
        __syncthreads();   // STS(c) visible on all warps; compute(c-1) finished
        const uint32_t* buf = base + (c & 1) * (32 * SWs);
#pragma unroll
        for (int h = 0; h < 4; ++h) {
            const int kc = c * 32 + h * 8;
            uint32_t a[2][4];
#pragma unroll
            for (int mf = 0; mf < 2; ++mf) {
                const float* r0 = sA + (mb + mf * 16 + g) * SA + kc;
                const float* r1 = r0 + 8 * SA;
                if (CVT_A) {
                    a[mf][0] = f2tf(r0[t]);     a[mf][1] = f2tf(r1[t]);
                    a[mf][2] = f2tf(r0[t + 4]); a[mf][3] = f2tf(r1[t + 4]);
                } else {
                    a[mf][0] = __float_as_uint(r0[t]);     a[mf][1] = __float_as_uint(r1[t]);
                    a[mf][2] = __float_as_uint(r0[t + 4]); a[mf][3] = __float_as_uint(r1[t + 4]);
                }
            }
            const uint32_t* b0r = buf + (h * 8 + t) * SWs + nbase + g;
            const uint32_t* b1r = b0r + 4 * SWs;
#pragma unroll
            for (int nt = 0; nt < 8; ++nt) {
                uint32_t b0 = b0r[nt * 8], b1 = b1r[nt * 8];
                mma_tf32(acc[0][nt], a[0][0], a[0][1], a[0][2], a[0][3], b0, b1);
                mma_tf32(acc[1][nt], a[1][0], a[1][1], a[1][2], a[1][3], b0, b1);
            }
        }
        if (c < 7) {
            uint32_t* dst = base + ((c + 1) & 1) * (32 * SWs) + tid;
#pragma unroll
            for (int i = 0; i < 8; ++i) {
                dst[(i * 4 + 0) * SWs] = f2tf(wreg[i].x);
                dst[(i * 4 + 1) * SWs] = f2tf(wreg[i].y);
                dst[(i * 4 + 2) * SWs] = f2tf(wreg[i].z);
                dst[(i * 4 + 3) * SWs] = f2tf(wreg[i].w);
            }
        }
    }
}

__global__ __launch_bounds__(256, 1)
void fusion_block_kernel(
    const float* __restrict__ Qg_, const float* __restrict__ Kg_,
    const float* __restrict__ Vg_, const float* __restrict__ Mg_,
    const float* __restrict__ W1, const float* __restrict__ b1,
    const float* __restrict__ W2, const float* __restrict__ b2,
    const float* __restrict__ ln1w, const float* __restrict__ ln1b,
    const float* __restrict__ ln2w, const float* __restrict__ ln2b,
    float* __restrict__ Out)
{
    extern __shared__ float sm[];
    float* sX = sm;                        // Q (fp32) -> x residual -> output
    float* sK = sm + Rr * SA;              // K (tf32 bits) -> H (tf32 bits)
    float* sV = sm + 2 * Rr * SA;          // V (tf32 bits, stride SV) -> W double buffer
    float* sS = sm + 2 * Rr * SA + Rr * SV;// scores fp32 -> probs (tf32 bits)

    const int tid  = threadIdx.x;
    const int warp = tid >> 5;
    const int lane = tid & 31;
    const int g    = lane >> 2;    // fragment group row
    const int t    = lane & 3;     // thread-in-group

    const int bid = blockIdx.x;
    const int bt  = bid / Dn;
    const int d   = bid - bt * Dn;
    const int b   = bt / Tn;
    const int bd  = b * Dn + d;

    const float* Qg = Qg_ + (size_t)bt  * (Un * En);
    const float* Kg = Kg_ + (size_t)bd  * (Pn * En);
    const float* Vg = Vg_ + (size_t)bd  * (Pn * En);
    const float* Mg = Mg_ + (size_t)bid * (Un * Pn);
    float*       Og = Out + (size_t)bid * (Un * En);

    // ---- Load tiles: Q fp32; K,V pre-rounded to tf32 bits; pad rows zero ----
    for (int f = tid; f < Rr * (En / 4); f += 256) {
        int row = f >> 6;
        int c4  = (f & 63) << 2;
        float4 z = make_float4(0.f, 0.f, 0.f, 0.f);
        float4 q = z, k = z, v = z;
        if (row < Un) {
            q = *reinterpret_cast<const float4*>(Qg + row * En + c4);
            k = *reinterpret_cast<const float4*>(Kg + row * En + c4);
            v = *reinterpret_cast<const float4*>(Vg + row * En + c4);
        }
        *reinterpret_cast<float4*>(&sX[row * SA + c4]) = q;
        *reinterpret_cast<float4*>(&sK[row * SA + c4]) =
            make_float4(tfr(k.x), tfr(k.y), tfr(k.z), tfr(k.w));
        *reinterpret_cast<float4*>(&sV[row * SV + c4]) =
            make_float4(tfr(v.x), tfr(v.y), tfr(v.z), tfr(v.w));
    }
    __syncthreads();

    // ---- S = Q K^T / 16 + mask  (tf32 MMA, m64n64k256; warp tile m32 x n16) ----
    {
        const int mbS = (warp & 1) * 32;
        const int nbS = (warp >> 1) * 16;
        float acc[2][2][4] = {};
#pragma unroll 4
        for (int k8 = 0; k8 < 32; ++k8) {
            const int kc = k8 * 8;
            uint32_t a[2][4];
#pragma unroll
            for (int mf = 0; mf < 2; ++mf) {
                const float* r0 = sX + (mbS + mf * 16 + g) * SA + kc;
                const float* r1 = r0 + 8 * SA;
                a[mf][0] = f2tf(r0[t]);     a[mf][1] = f2tf(r1[t]);
                a[mf][2] = f2tf(r0[t + 4]); a[mf][3] = f2tf(r1[t + 4]);
            }
#pragma unroll
            for (int nt = 0; nt < 2; ++nt) {
                const float* kcol = sK + (nbS + nt * 8 + g) * SA + kc;
                uint32_t b0 = __float_as_uint(kcol[t]);
                uint32_t b1 = __float_as_uint(kcol[t + 4]);
                mma_tf32(acc[0][nt], a[0][0], a[0][1], a[0][2], a[0][3], b0, b1);
                mma_tf32(acc[1][nt], a[1][0], a[1][1], a[1][2], a[1][3], b0, b1);
            }
        }
        const float inv_scale = 1.0f / 16.0f;   // sqrt(256)+1e-8 == 16.0f in fp32
#pragma unroll
        for (int mf = 0; mf < 2; ++mf) {
#pragma unroll
            for (int nt = 0; nt < 2; ++nt) {
#pragma unroll
                for (int r = 0; r < 4; ++r) {
                    int u = mbS + mf * 16 + g + (r >= 2 ? 8 : 0);
                    int p = nbS + nt * 8 + 2 * t + (r & 1);
                    float s = acc[mf][nt][r] * inv_scale;
                    if (u < Un && p < Pn) s += Mg[u * Pn + p];
                    sS[u * SSs + p] = s;
                }
            }
        }
    }
    __syncthreads();

    // ---- softmax over p (valid p<50); write probs as tf32 bits; pad cols 0 ----
    {
#pragma unroll
        for (int r = 0; r < 8; ++r) {
            int row = warp * 8 + r;
            float v0 = sS[row * SSs + lane];
            float v1 = (lane + 32 < Pn) ? sS[row * SSs + lane + 32] : -1e30f;
            float m  = wmax(fmaxf(v0, v1));
            float e0 = __expf(v0 - m);
            float e1 = (lane + 32 < Pn) ? __expf(v1 - m) : 0.f;
            float inv = 1.f / wsum(e0 + e1);
            sS[row * SSs + lane]      = tfr(e0 * inv);
            sS[row * SSs + lane + 32] = tfr(e1 * inv);
        }
    }
    __syncthreads();

    const int mb = (warp & 1) * 32;
    const int nb = (warp >> 1) * 64;

    // ---- v_att = S @ V (tf32 MMA, m64n256k64; warp m32 x n64); x = Q + v_att ----
    {
        float acc[2][8][4] = {};
#pragma unroll
        for (int k8 = 0; k8 < 8; ++k8) {
            const int kc = k8 * 8;
            uint32_t a[2][4];
#pragma unroll
            for (int mf = 0; mf < 2; ++mf) {
                const float* r0 = sS + (mb + mf * 16 + g) * SSs + kc;
                const float* r1 = r0 + 8 * SSs;
                a[mf][0] = __float_as_uint(r0[t]);     a[mf][1] = __float_as_uint(r1[t]);
                a[mf][2] = __float_as_uint(r0[t + 4]); a[mf][3] = __float_as_uint(r1[t + 4]);
            }
            const uint32_t* vb0 = reinterpret_cast<const uint32_t*>(sV) + (kc + t) * SV + nb + g;
            const uint32_t* vb1 = vb0 + 4 * SV;
#pragma unroll
            for (int nt = 0; nt < 8; ++nt) {
                uint32_t b0 = vb0[nt * 8], b1 = vb1[nt * 8];
                mma_tf32(acc[0][nt], a[0][0], a[0][1], a[0][2], a[0][3], b0, b1);
                mma_tf32(acc[1][nt], a[1][0], a[1][1], a[1][2], a[1][3], b0, b1);
            }
        }
#pragma unroll
        for (int mf = 0; mf < 2; ++mf) {
#pragma unroll
            for (int nt = 0; nt < 8; ++nt) {
                int row0 = mb + mf * 16 + g;
                int col  = nb + nt * 8 + 2 * t;
                sX[row0 * SA + col]           += acc[mf][nt][0];
                sX[row0 * SA + col + 1]       += acc[mf][nt][1];
                sX[(row0 + 8) * SA + col]     += acc[mf][nt][2];
                sX[(row0 + 8) * SA + col + 1] += acc[mf][nt][3];
            }
        }
    }
    __syncthreads();

    // ---- LN1 (one warp per 8 rows), x stays fp32 in sX ----
    {
#pragma unroll
        for (int r = 0; r < 8; ++r) {
            int row = warp * 8 + r;
            float xv[8];
            float s = 0.f;
#pragma unroll
            for (int kk = 0; kk < 8; ++kk) { xv[kk] = sX[row * SA + lane + kk * 32]; s += xv[kk]; }
            float mu = wsum(s) * (1.f / En);
            float vs = 0.f;
#pragma unroll
            for (int kk = 0; kk < 8; ++kk) { float t2 = xv[kk] - mu; vs += t2 * t2; }
            float rstd = rsqrtf(wsum(vs) * (1.f / En) + 1e-5f);
#pragma unroll
            for (int kk = 0; kk < 8; ++kk) {
                int col = lane + kk * 32;
                sX[row * SA + col] = (xv[kk] - mu) * rstd * ln1w[col] + ln1b[col];
            }
        }
    }
    // (first barrier inside ffn_mma orders LN1 writes + retires V region)

    // ---- FFN1: H = relu(x @ W1^T + b1) -> sK as tf32 bits ----
    {
        float acc[2][8][4] = {};
        ffn_mma<true>(W1, sX, sV, acc, tid, g, t, mb, nb);
#pragma unroll
        for (int mf = 0; mf < 2; ++mf) {
#pragma unroll
            for (int nt = 0; nt < 8; ++nt) {
                int row0 = mb + mf * 16 + g;
                int col  = nb + nt * 8 + 2 * t;
                float bb0 = __ldg(b1 + col), bb1 = __ldg(b1 + col + 1);
                sK[row0 * SA + col]           = tfr(fmaxf(acc[mf][nt][0] + bb0, 0.f));
                sK[row0 * SA + col + 1]       = tfr(fmaxf(acc[mf][nt][1] + bb1, 0.f));
                sK[(row0 + 8) * SA + col]     = tfr(fmaxf(acc[mf][nt][2] + bb0, 0.f));
                sK[(row0 + 8) * SA + col + 1] = tfr(fmaxf(acc[mf][nt][3] + bb1, 0.f));
            }
        }
    }
    // (first barrier inside next ffn_mma orders H writes)

    // ---- FFN2: y = H @ W2^T + b2 + x  (accumulate into sX, fp32) ----
    {
        float acc[2][8][4] = {};
        ffn_mma<false>(W2, sK, sV, acc, tid, g, t, mb, nb);
#pragma unroll
        for (int mf = 0; mf < 2; ++mf) {
#pragma unroll
            for (int nt = 0; nt < 8; ++nt) {
                int row0 = mb + mf * 16 + g;
                int col  = nb + nt * 8 + 2 * t;
                float bb0 = __ldg(b2 + col), bb1 = __ldg(b2 + col + 1);
                sX[row0 * SA + col]           += acc[mf][nt][0] + bb0;
                sX[row0 * SA + col + 1]       += acc[mf][nt][1] + bb1;
                sX[(row0 + 8) * SA + col]     += acc[mf][nt][2] + bb0;
                sX[(row0 + 8) * SA + col + 1] += acc[mf][nt][3] + bb1;
            }
        }
    }
    __syncthreads();

    // ---- LN2 + store (valid rows only) ----
    {
#pragma unroll
        for (int r = 0; r < 8; ++r) {
            int row = warp * 8 + r;
            if (row >= Un) break;    // uniform per warp
            float xv[8];
            float s = 0.f;
#pragma unroll
            for (int kk = 0; kk < 8; ++kk) { xv[kk] = sX[row * SA + lane + kk * 32]; s += xv[kk]; }
            float mu = wsum(s) * (1.f / En);
            float vs = 0.f;
#pragma unroll
            for (int kk = 0; kk < 8; ++kk) { float t2 = xv[kk] - mu; vs += t2 * t2; }
            float rstd = rsqrtf(wsum(vs) * (1.f / En) + 1e-5f);
#pragma unroll
            for (int kk = 0; kk < 8; ++kk) {
                int col = lane + kk * 32;
                Og[row * En + col] = (xv[kk] - mu) * rstd * ln2w[col] + ln2b[col];
            }
        }
    }
}

extern "C" void kernel_launch(void* const* d_in, const int* in_sizes, int n_in,
                              void* d_out, int out_size) {
    (void)in_sizes; (void)n_in; (void)out_size;
    cudaFuncSetAttribute(fusion_block_kernel,
                         cudaFuncAttributeMaxDynamicSharedMemorySize, SMEM_BYTES);
    fusion_block_kernel<<<Bn * Tn * Dn, 256, SMEM_BYTES>>>(
        (const float*)d_in[0],  // Q
        (const float*)d_in[1],  // K
        (const float*)d_in[2],  // V
        (const float*)d_in[3],  // attention_mask
        (const float*)d_in[4],  // W1
        (const float*)d_in[5],  // b1
        (const float*)d_in[6],  // W2
        (const float*)d_in[7],  // b2
        (const float*)d_in[8],  // ln1_w
        (const float*)d_in[9],  // ln1_b
        (const float*)d_in[10], // ln2_w
        (const float*)d_in[11], // ln2_b
        (float*)d_out);
}

// round 10
// speedup vs baseline: 1.9864x; 1.1366x over previous
#include <cuda_runtime.h>
#include <cstdint>

// Problem dims
static constexpr int Bn = 32, Tn = 10, Dn = 10, Un = 50, Pn = 50, En = 256;
static constexpr int Rr = 64;
static constexpr int SA  = 260;  // sX/sK row stride (floats); 260%32==4
static constexpr int SSs = 68;   // sS row stride; 68%32==4
static constexpr int SVT = 68;   // sVT row stride (256 e-rows x (64 p + pad))
static constexpr int SWr = 36;   // staged W row stride (256 n-rows x (32 k + pad))

static constexpr int OFF_X  = 0;
static constexpr int OFF_K  = Rr * SA;                 // 16640
static constexpr int OFF_R3 = 2 * Rr * SA;             // 33280 (sVT 17408 | Wbuf 18432)
static constexpr int OFF_S  = OFF_R3 + 2 * 256 * SWr;  // 51712
static constexpr int SMEM_FLOATS = OFF_S + Rr * SSs;   // 56064
static constexpr int SMEM_BYTES  = SMEM_FLOATS * 4;    // 224256 (< 227KB opt-in cap)

// in-32-block k permutation: sigma(k) = (k%4)*8 + (k%32)/4  (+ block base)
__device__ __forceinline__ int perm32(int c) { return (c & ~31) | (((c & 3) << 3) | ((c & 31) >> 2)); }
__device__ __forceinline__ int inv32lo(int l) { return ((l & 7) << 2) | ((l & 31) >> 3); }  // l in [0,32)

__device__ __forceinline__ float wsum(float v) {
#pragma unroll
    for (int o = 16; o > 0; o >>= 1) v += __shfl_xor_sync(0xffffffffu, v, o);
    return v;
}
__device__ __forceinline__ float wmax(float v) {
#pragma unroll
    for (int o = 16; o > 0; o >>= 1) v = fmaxf(v, __shfl_xor_sync(0xffffffffu, v, o));
    return v;
}

#define F4E(v, i) ((i) == 0 ? (v).x : (i) == 1 ? (v).y : (i) == 2 ? (v).z : (v).w)
#define BITS(v, i) __float_as_uint(F4E(v, i))

// raw fp32 bits as tf32 operands (HW ignores low 13 mantissa bits)
__device__ __forceinline__ void mma_tf32(float c[4],
                                         uint32_t a0, uint32_t a1, uint32_t a2, uint32_t a3,
                                         uint32_t b0, uint32_t b1) {
    asm("mma.sync.aligned.m16n8k8.row.col.f32.tf32.tf32.f32 "
        "{%0,%1,%2,%3}, {%4,%5,%6,%7}, {%8,%9}, {%0,%1,%2,%3};"
        : "+f"(c[0]), "+f"(c[1]), "+f"(c[2]), "+f"(c[3])
        : "r"(a0), "r"(a1), "r"(a2), "r"(a3), "r"(b0), "r"(b1));
}

// stage one W row (32 k, already in 8 float4 regs, k-local 0..31) into n-major
// k-permuted layout: granule (2*j0+half) = elems j0 of quads (half*4..half*4+3).
__device__ __forceinline__ void stage_w(float* buf, int n, const float4 w[8]) {
    float* dst = buf + n * SWr;
#pragma unroll
    for (int j0 = 0; j0 < 4; ++j0) {
        float4 ge = make_float4(F4E(w[0], j0), F4E(w[1], j0), F4E(w[2], j0), F4E(w[3], j0));
        float4 go = make_float4(F4E(w[4], j0), F4E(w[5], j0), F4E(w[6], j0), F4E(w[7], j0));
        *reinterpret_cast<float4*>(dst + j0 * 8)     = ge;   // granule 2*j0
        *reinterpret_cast<float4*>(dst + j0 * 8 + 4) = go;   // granule 2*j0+1
    }
}

// C[64][256] = A[64][256] @ W^T.  A in smem (E-permuted, stride SA), W global
// [256n][256k] row-major staged n-major k-permuted, double-buffered 32-k chunks.
// Warp tile m32 x n64: mb=(warp&1)*32, nb=(warp>>2? no: warp>>1)*64.
__device__ __forceinline__ void ffn_mma(
    const float* __restrict__ Wg, const float* __restrict__ sA, float* __restrict__ sWb,
    float acc[2][8][4], int tid, int g, int t, int mb, int nb)
{
    float4 wreg[8];
    const float* wrow = Wg + tid * En;
#pragma unroll
    for (int i = 0; i < 8; ++i)
        wreg[i] = *reinterpret_cast<const float4*>(wrow + i * 4);
    __syncthreads();                 // prior phase done: sA final, sWb region free
    stage_w(sWb, tid, wreg);
    for (int c = 0; c < 8; ++c) {
        if (c < 7) {
#pragma unroll
            for (int i = 0; i < 8; ++i)
                wreg[i] = *reinterpret_cast<const float4*>(wrow + (c + 1) * 32 + i * 4);
        }
        __syncthreads();             // stage(c) visible; compute(c-1) finished
        const float* buf = sWb + (c & 1) * (256 * SWr);
        float4 aA[4][2];
#pragma unroll
        for (int r4 = 0; r4 < 4; ++r4) {
            int row = mb + (r4 & 1) * 8 + (r4 >> 1) * 16 + g;
            const float* p = sA + row * SA + c * 32 + 8 * t;
            aA[r4][0] = *reinterpret_cast<const float4*>(p);
            aA[r4][1] = *reinterpret_cast<const float4*>(p + 4);
        }
#pragma unroll
        for (int ntg = 0; ntg < 2; ++ntg) {
            float4 bB[4][2];
#pragma unroll
            for (int q = 0; q < 4; ++q) {
                int n = nb + (ntg * 4 + q) * 8 + g;
                const float* p = buf + n * SWr + 8 * t;
                bB[q][0] = *reinterpret_cast<const float4*>(p);
                bB[q][1] = *reinterpret_cast<const float4*>(p + 4);
            }
#pragma unroll
            for (int h = 0; h < 4; ++h) {
                const int sel = h >> 1, e0 = 2 * (h & 1), e1 = e0 + 1;
#pragma unroll
                for (int q = 0; q < 4; ++q) {
                    uint32_t b0 = BITS(bB[q][sel], e0), b1 = BITS(bB[q][sel], e1);
#pragma unroll
                    for (int mf = 0; mf < 2; ++mf) {
                        mma_tf32(acc[mf][ntg * 4 + q],
                                 BITS(aA[2 * mf][sel], e0), BITS(aA[2 * mf + 1][sel], e0),
                                 BITS(aA[2 * mf][sel], e1), BITS(aA[2 * mf + 1][sel], e1),
                                 b0, b1);
                    }
                }
            }
        }
        if (c < 7)
            stage_w(sWb + ((c + 1) & 1) * (256 * SWr), tid, wreg);
    }
}

__global__ __launch_bounds__(256, 1)
void fusion_block_kernel(
    const float* __restrict__ Qg_, const float* __restrict__ Kg_,
    const float* __restrict__ Vg_, const float* __restrict__ Mg_,
    const float* __restrict__ W1, const float* __restrict__ b1,
    const float* __restrict__ W2, const float* __restrict__ b2,
    const float* __restrict__ ln1w, const float* __restrict__ ln1b,
    const float* __restrict__ ln2w, const float* __restrict__ ln2b,
    float* __restrict__ Out)
{
    extern __shared__ float sm[];
    float* sX  = sm + OFF_X;    // Q -> x residual (E-permuted cols, fp32)
    float* sK  = sm + OFF_K;    // K (E-perm) -> H (E2-perm)
    float* sR3 = sm + OFF_R3;   // sVT [256 e][p-perm] -> W double buffer
    float* sS  = sm + OFF_S;    // scores/probs (p-permuted cols)

    const int tid  = threadIdx.x;
    const int warp = tid >> 5;
    const int lane = tid & 31;
    const int g    = lane >> 2;
    const int t    = lane & 3;

    const int bid = blockIdx.x;
    const int bt  = bid / Dn;
    const int d   = bid - bt * Dn;
    const int b   = bt / Tn;
    const int bd  = b * Dn + d;

    const float* Qg = Qg_ + (size_t)bt  * (Un * En);
    const float* Kg = Kg_ + (size_t)bd  * (Pn * En);
    const float* Vg = Vg_ + (size_t)bd  * (Pn * En);
    const float* Mg = Mg_ + (size_t)bid * (Un * Pn);
    float*       Og = Out + (size_t)bid * (Un * En);

    const float4 z4 = make_float4(0.f, 0.f, 0.f, 0.f);

    // ---- Load Q,K (E-permuted, granule-assembled, conflict-free STS.128) ----
#pragma unroll
    for (int it = 0; it < 4; ++it) {
        int idx = tid + it * 256;      // 64 rows x 16 half-blocks
        int row = idx & 63;
        int hb  = idx >> 6;            // half-block of 16 e
        float4 q[4], k[4];
#pragma unroll
        for (int m = 0; m < 4; ++m) {
            if (row < Un) {
                q[m] = *reinterpret_cast<const float4*>(Qg + row * En + hb * 16 + m * 4);
                k[m] = *reinterpret_cast<const float4*>(Kg + row * En + hb * 16 + m * 4);
            } else { q[m] = z4; k[m] = z4; }
        }
        int dst = row * SA + (hb >> 1) * 32 + (hb & 1) * 4;
#pragma unroll
        for (int j0 = 0; j0 < 4; ++j0) {
            *reinterpret_cast<float4*>(sX + dst + j0 * 8) =
                make_float4(F4E(q[0], j0), F4E(q[1], j0), F4E(q[2], j0), F4E(q[3], j0));
            *reinterpret_cast<float4*>(sK + dst + j0 * 8) =
                make_float4(F4E(k[0], j0), F4E(k[1], j0), F4E(k[2], j0), F4E(k[3], j0));
        }
    }
    // ---- Load V transposed: sVT[e][perm(p)] (lanes across p -> conflict-free) ----
#pragma unroll
    for (int it = 0; it < 16; ++it) {
        int idx = tid + it * 256;      // 64 p x 64 e-quads
        int p   = idx & 63;
        int eq  = idx >> 6;
        float4 v = (p < Un) ? *reinterpret_cast<const float4*>(Vg + p * En + eq * 4) : z4;
        int sp = perm32(p);
#pragma unroll
        for (int j = 0; j < 4; ++j)
            sR3[(eq * 4 + j) * SVT + sp] = F4E(v, j);
    }
    __syncthreads();

    // ---- S = Q K^T / 16 + mask  (warp tile m32 x n16) ----
    {
        const int mbS = (warp & 1) * 32;
        const int nbS = (warp >> 1) * 16;
        float acc[2][2][4] = {};
#pragma unroll
        for (int kb = 0; kb < 8; ++kb) {
            float4 aA[4][2];
#pragma unroll
            for (int r4 = 0; r4 < 4; ++r4) {
                int row = mbS + (r4 & 1) * 8 + (r4 >> 1) * 16 + g;
                const float* p = sX + row * SA + kb * 32 + 8 * t;
                aA[r4][0] = *reinterpret_cast<const float4*>(p);
                aA[r4][1] = *reinterpret_cast<const float4*>(p + 4);
            }
            float4 bB[2][2];
#pragma unroll
            for (int nt = 0; nt < 2; ++nt) {
                const float* p = sK + (nbS + nt * 8 + g) * SA + kb * 32 + 8 * t;
                bB[nt][0] = *reinterpret_cast<const float4*>(p);
                bB[nt][1] = *reinterpret_cast<const float4*>(p + 4);
            }
#pragma unroll
            for (int h = 0; h < 4; ++h) {
                const int sel = h >> 1, e0 = 2 * (h & 1), e1 = e0 + 1;
#pragma unroll
                for (int nt = 0; nt < 2; ++nt) {
                    uint32_t b0 = BITS(bB[nt][sel], e0), b1 = BITS(bB[nt][sel], e1);
#pragma unroll
                    for (int mf = 0; mf < 2; ++mf)
                        mma_tf32(acc[mf][nt],
                                 BITS(aA[2 * mf][sel], e0), BITS(aA[2 * mf + 1][sel], e0),
                                 BITS(aA[2 * mf][sel], e1), BITS(aA[2 * mf + 1][sel], e1),
                                 b0, b1);
                }
            }
        }
        const float inv_scale = 1.0f / 16.0f;  // sqrt(256)+1e-8 == 16.0f
#pragma unroll
        for (int mf = 0; mf < 2; ++mf)
#pragma unroll
            for (int nt = 0; nt < 2; ++nt)
#pragma unroll
                for (int r = 0; r < 4; ++r) {
                    int u = mbS + mf * 16 + g + (r >= 2 ? 8 : 0);
                    int p = nbS + nt * 8 + 2 * t + (r & 1);
                    float s = acc[mf][nt][r] * inv_scale;
                    if (u < Un && p < Pn) s += Mg[u * Pn + p];
                    sS[u * SSs + perm32(p)] = s;
                }
    }
    __syncthreads();

    // ---- softmax over p (cols are p-permuted; validity via inverse perm) ----
    {
        const bool val1 = (inv32lo(lane) < Pn - 32);   // p = 32 + inv < 50
#pragma unroll
        for (int r = 0; r < 8; ++r) {
            int row = warp * 8 + r;
            float v0 = sS[row * SSs + lane];           // p = inv32lo(lane) < 32, always valid
            float v1 = val1 ? sS[row * SSs + lane + 32] : -1e30f;
            float m  = wmax(fmaxf(v0, v1));
            float e0 = __expf(v0 - m);
            float e1 = val1 ? __expf(v1 - m) : 0.f;
            float inv = 1.f / wsum(e0 + e1);
            sS[row * SSs + lane]      = e0 * inv;
            sS[row * SSs + lane + 32] = e1 * inv;
        }
    }
    __syncthreads();

    const int mb = (warp & 1) * 32;
    const int nb = (warp >> 1) * 64;

    // ---- v_att = S @ V (A: probs p-perm; B: sVT e-rows, p-perm cols); x += ----
    {
        float acc[2][8][4] = {};
#pragma unroll
        for (int kb = 0; kb < 2; ++kb) {
            float4 aA[4][2];
#pragma unroll
            for (int r4 = 0; r4 < 4; ++r4) {
                int row = mb + (r4 & 1) * 8 + (r4 >> 1) * 16 + g;
                const float* p = sS + row * SSs + kb * 32 + 8 * t;
                aA[r4][0] = *reinterpret_cast<const float4*>(p);
                aA[r4][1] = *reinterpret_cast<const float4*>(p + 4);
            }
#pragma unroll
            for (int ntg = 0; ntg < 2; ++ntg) {
                float4 bB[4][2];
#pragma unroll
                for (int q = 0; q < 4; ++q) {
                    const float* p = sR3 + (nb + (ntg * 4 + q) * 8 + g) * SVT + kb * 32 + 8 * t;
                    bB[q][0] = *reinterpret_cast<const float4*>(p);
                    bB[q][1] = *reinterpret_cast<const float4*>(p + 4);
                }
#pragma unroll
                for (int h = 0; h < 4; ++h) {
                    const int sel = h >> 1, e0 = 2 * (h & 1), e1 = e0 + 1;
#pragma unroll
                    for (int q = 0; q < 4; ++q) {
                        uint32_t b0 = BITS(bB[q][sel], e0), b1 = BITS(bB[q][sel], e1);
#pragma unroll
                        for (int mf = 0; mf < 2; ++mf)
                            mma_tf32(acc[mf][ntg * 4 + q],
                                     BITS(aA[2 * mf][sel], e0), BITS(aA[2 * mf + 1][sel], e0),
                                     BITS(aA[2 * mf][sel], e1), BITS(aA[2 * mf + 1][sel], e1),
                                     b0, b1);
                    }
                }
            }
        }
#pragma unroll
        for (int mf = 0; mf < 2; ++mf)
#pragma unroll
            for (int nt = 0; nt < 8; ++nt) {
                int row0 = mb + mf * 16 + g;
                int col  = nb + nt * 8 + 2 * t;
                int sc0 = perm32(col), sc1 = perm32(col + 1);
                sX[row0 * SA + sc0]       += acc[mf][nt][0];
                sX[row0 * SA + sc1]       += acc[mf][nt][1];
                sX[(row0 + 8) * SA + sc0] += acc[mf][nt][2];
                sX[(row0 + 8) * SA + sc1] += acc[mf][nt][3];
            }
    }
    __syncthreads();

    // ---- LN1 (perm cols; weights via inverse perm) ----
    {
#pragma unroll
        for (int r = 0; r < 8; ++r) {
            int row = warp * 8 + r;
            float xv[8];
            float s = 0.f;
#pragma unroll
            for (int kk = 0; kk < 8; ++kk) { xv[kk] = sX[row * SA + lane + kk * 32]; s += xv[kk]; }
            float mu = wsum(s) * (1.f / En);
            float vs = 0.f;
#pragma unroll
            for (int kk = 0; kk < 8; ++kk) { float t2 = xv[kk] - mu; vs += t2 * t2; }
            float rstd = rsqrtf(wsum(vs) * (1.f / En) + 1e-5f);
            int eb = inv32lo(lane);
#pragma unroll
            for (int kk = 0; kk < 8; ++kk) {
                int e = kk * 32 + eb;
                sX[row * SA + lane + kk * 32] = (xv[kk] - mu) * rstd * ln1w[e] + ln1b[e];
            }
        }
    }
    // (first barrier inside ffn_mma orders LN1 writes, retires sVT region)

    // ---- FFN1: H = relu(x @ W1^T + b1) -> sK (E2-permuted cols) ----
    {
        float acc[2][8][4] = {};
        ffn_mma(W1, sX, sR3, acc, tid, g, t, mb, nb);
#pragma unroll
        for (int mf = 0; mf < 2; ++mf)
#pragma unroll
            for (int nt = 0; nt < 8; ++nt) {
                int row0 = mb + mf * 16 + g;
                int col  = nb + nt * 8 + 2 * t;
                float bb0 = __ldg(b1 + col), bb1 = __ldg(b1 + col + 1);
                int sc0 = perm32(col), sc1 = perm32(col + 1);
                sK[row0 * SA + sc0]       = fmaxf(acc[mf][nt][0] + bb0, 0.f);
                sK[row0 * SA + sc1]       = fmaxf(acc[mf][nt][1] + bb1, 0.f);
                sK[(row0 + 8) * SA + sc0] = fmaxf(acc[mf][nt][2] + bb0, 0.f);
                sK[(row0 + 8) * SA + sc1] = fmaxf(acc[mf][nt][3] + bb1, 0.f);
            }
    }

    // ---- FFN2: y = H @ W2^T + b2 + x (into sX, fp32) ----
    {
        float acc[2][8][4] = {};
        ffn_mma(W2, sK, sR3, acc, tid, g, t, mb, nb);
#pragma unroll
        for (int mf = 0; mf < 2; ++mf)
#pragma unroll
            for (int nt = 0; nt < 8; ++nt) {
                int row0 = mb + mf * 16 + g;
                int col  = nb + nt * 8 + 2 * t;
                float bb0 = __ldg(b2 + col), bb1 = __ldg(b2 + col + 1);
                int sc0 = perm32(col), sc1 = perm32(col + 1);
                sX[row0 * SA + sc0]       += acc[mf][nt][0] + bb0;
                sX[row0 * SA + sc1]       += acc[mf][nt][1] + bb1;
                sX[(row0 + 8) * SA + sc0] += acc[mf][nt][2] + bb0;
                sX[(row0 + 8) * SA + sc1] += acc[mf][nt][3] + bb1;
            }
    }
    __syncthreads();

    // ---- LN2 + store (de-permute via inverse; stays line-coalesced) ----
    {
#pragma unroll
        for (int r = 0; r < 8; ++r) {
            int row = warp * 8 + r;
            if (row >= Un) break;    // uniform per warp
            float xv[8];
            float s = 0.f;
#pragma unroll
            for (int kk = 0; kk < 8; ++kk) { xv[kk] = sX[row * SA + lane + kk * 32]; s += xv[kk]; }
            float mu = wsum(s) * (1.f / En);
            float vs = 0.f;
#pragma unroll
            for (int kk = 0; kk < 8; ++kk) { float t2 = xv[kk] - mu; vs += t2 * t2; }
            float rstd = rsqrtf(wsum(vs) * (1.f / En) + 1e-5f);
            int eb = inv32lo(lane);
#pragma unroll
            for (int kk = 0; kk < 8; ++kk) {
                int e = kk * 32 + eb;
                Og[row * En + e] = (xv[kk] - mu) * rstd * ln2w[e] + ln2b[e];
            }
        }
    }
}

extern "C" void kernel_launch(void* const* d_in, const int* in_sizes, int n_in,
                              void* d_out, int out_size) {
    (void)in_sizes; (void)n_in; (void)out_size;
    cudaFuncSetAttribute(fusion_block_kernel,
                         cudaFuncAttributeMaxDynamicSharedMemorySize, SMEM_BYTES);
    fusion_block_kernel<<<Bn * Tn * Dn, 256, SMEM_BYTES>>>(
        (const float*)d_in[0],  // Q
        (const float*)d_in[1],  // K
        (const float*)d_in[2],  // V
        (const float*)d_in[3],  // attention_mask
        (const float*)d_in[4],  // W1
        (const float*)d_in[5],  // b1
        (const float*)d_in[6],  // W2
        (const float*)d_in[7],  // b2
        (const float*)d_in[8],  // ln1_w
        (const float*)d_in[9],  // ln1_b
        (const float*)d_in[10], // ln2_w
        (const float*)d_in[11], // ln2_b
        (float*)d_out);
}